// round 16
// baseline (speedup 1.0000x reference)
#include <cuda_runtime.h>
#include <cuda_bf16.h>
#include <cstdint>

constexpr int B  = 4;
constexpr int C  = 512;
constexpr int T  = 3;
constexpr int HW = 2304;   // 48*48
constexpr int N3 = 6912;   // 3*HW
constexpr int G  = 4;
constexpr int CG = C / G;  // 128
constexpr int KQ = 3 * C;  // 1536: split-bf16 concat K for q
constexpr float EPS = 1e-6f;
constexpr float ALPHA = 0.044194173824159216f;  // C^-0.5

typedef __nv_bfloat16  bf16;
typedef __nv_bfloat162 bf162;

// Scratch
__device__ bf16  gb_hnt [(size_t)B * N3 * C];   // hn transposed [b][m][c]
__device__ bf16  gb_hncm[(size_t)B * C * N3];   // hn [b][c][m]
__device__ bf16  gb_hq  [(size_t)B * HW * KQ];  // t=1 slice split [hi|lo|hi]
__device__ float g_qt   [(size_t)B * HW * C];   // q fp32 (skip)
__device__ bf16  gb_qw2 [(size_t)B * HW * C];   // hn1*Wt + g  [p][c]
__device__ bf16  gb_sc  [(size_t)B * HW * N3];  // exp(scores) [p][m]
__device__ bf16  gb_u   [(size_t)B * HW * C];   // u = e*hn [p][j]
__device__ bf16  gb_pw[C * C];                  // proj weight bf16 [o][c]
__device__ bf16  gb_qwT[C * C], gb_kwT[C * C], gb_vwT[C * C];  // transposed bf16
__device__ bf16  gb_wt[C * C];                  // Wt[c][j] = sum_o kw[o][c] qw[o][j]
__device__ bf16  gb_mm[C * C];                  // M[o][j]  = sum_c pw[o][c] vw[c][j]
__device__ bf16  gb_qw[C * KQ];                 // q weights split [hi|hi|lo]
__device__ float g_g  [C];                      // g[c] = sum_o qb[o] kw[o][c]
__device__ float g_b2 [C];                      // bias2[o] = sum_c pw[o][c] vb[c] + pb[o]
__device__ float g_stats[2 * B * G];
__device__ float g_Z[(size_t)B * HW];           // softmax denominators

__device__ __forceinline__ uint32_t smem_u32(const void* p) {
    return (uint32_t)__cvta_generic_to_shared(p);
}
#define CP_ASYNC16(sm, gm) \
    asm volatile("cp.async.cg.shared.global [%0], [%1], 16;" :: "r"(sm), "l"(gm))
#define CP_COMMIT asm volatile("cp.async.commit_group;")
#define CP_WAIT1  asm volatile("cp.async.wait_group 1;")
#define CP_WAIT0  asm volatile("cp.async.wait_group 0;")

__device__ __forceinline__ void ldm_x4(uint32_t* r, uint32_t addr) {
    asm volatile("ldmatrix.sync.aligned.m8n8.x4.shared.b16 {%0,%1,%2,%3}, [%4];"
        : "=r"(r[0]), "=r"(r[1]), "=r"(r[2]), "=r"(r[3]) : "r"(addr));
}
__device__ __forceinline__ void mma_bf16(float* c, const uint32_t* a, const uint32_t* b) {
    asm volatile("mma.sync.aligned.m16n8k16.row.col.f32.bf16.bf16.f32 "
        "{%0,%1,%2,%3}, {%4,%5,%6,%7}, {%8,%9}, {%0,%1,%2,%3};"
        : "+f"(c[0]), "+f"(c[1]), "+f"(c[2]), "+f"(c[3])
        : "r"(a[0]), "r"(a[1]), "r"(a[2]), "r"(a[3]), "r"(b[0]), "r"(b[1]));
}

// ---------------------------------------------------------------------------
// GroupNorm stats
// ---------------------------------------------------------------------------
__global__ void gn_stats_kernel(const float* __restrict__ x) {
    const int bg = blockIdx.x;
    const int b = bg >> 2, g = bg & 3;
    const int TOT4 = CG * T * HW / 4;
    const int PER  = TOT4 / 16;
    const int start = blockIdx.y * PER;

    float s = 0.f, ss = 0.f;
    for (int i = start + threadIdx.x; i < start + PER; i += blockDim.x) {
        int cl = i / (T * HW / 4);
        int r  = i - cl * (T * HW / 4);
        int t  = r / (HW / 4);
        int p4 = r - t * (HW / 4);
        float4 v = reinterpret_cast<const float4*>(x)[
            ((size_t)(t * B + b) * C + g * CG + cl) * (HW / 4) + p4];
        s  += v.x + v.y + v.z + v.w;
        ss += v.x * v.x + v.y * v.y + v.z * v.z + v.w * v.w;
    }
    __shared__ float rs[8], rss[8];
    #pragma unroll
    for (int o = 16; o; o >>= 1) {
        s  += __shfl_xor_sync(0xffffffffu, s, o);
        ss += __shfl_xor_sync(0xffffffffu, ss, o);
    }
    if ((threadIdx.x & 31) == 0) { rs[threadIdx.x >> 5] = s; rss[threadIdx.x >> 5] = ss; }
    __syncthreads();
    if (threadIdx.x == 0) {
        float a = 0.f, c = 0.f;
        #pragma unroll
        for (int i = 0; i < 8; i++) { a += rs[i]; c += rss[i]; }
        atomicAdd(&g_stats[2 * bg],     a);
        atomicAdd(&g_stats[2 * bg + 1], c);
    }
}

// normalize + affine; write hncm [c][m], hnt [m][c], hq split (t=1)
__global__ void gn_apply_t_kernel(const float* __restrict__ x,
                                  const float* __restrict__ scale,
                                  const float* __restrict__ bias) {
    __shared__ float tile[32][33];
    const int bt = blockIdx.z;
    const int b = bt / T, t = bt - b * T;
    const int p0 = blockIdx.x << 5, c0 = blockIdx.y << 5;
    const int tx = threadIdx.x, ty = threadIdx.y;  // 32 x 8
    const float nrm = 1.f / (float)(CG * T * HW);

    #pragma unroll
    for (int kk = 0; kk < 4; kk++) {
        int c = c0 + ty + kk * 8;
        int g = c >> 7;
        float sum = g_stats[2 * (b * G + g)];
        float sq  = g_stats[2 * (b * G + g) + 1];
        float mean = sum * nrm;
        float var  = sq * nrm - mean * mean;
        float rstd = rsqrtf(var + EPS);
        float a = rstd * scale[c];
        float d = bias[c] - mean * a;
        float v = x[((size_t)(t * B + b) * C + c) * HW + p0 + tx];
        tile[ty + kk * 8][tx] = v * a + d;
        gb_hncm[(size_t)b * C * N3 + (size_t)c * N3 + t * HW + p0 + tx] =
            __float2bfloat16(v * a + d);
    }
    __syncthreads();
    #pragma unroll
    for (int kk = 0; kk < 4; kk++) {
        int p = p0 + ty + kk * 8;
        float v = tile[tx][ty + kk * 8];
        bf16 hi = __float2bfloat16(v);
        gb_hnt[(size_t)b * N3 * C + (size_t)(t * HW + p) * C + c0 + tx] = hi;
        if (t == 1) {
            bf16 lo = __float2bfloat16(v - __bfloat162float(hi));
            size_t base = ((size_t)b * HW + p) * KQ + c0 + tx;
            gb_hq[base]            = hi;
            gb_hq[base + C]        = lo;
            gb_hq[base + 2 * C]    = hi;
        }
    }
}

// zero Z/stats; pw->bf16; q weights split [hi|hi|lo]
__global__ void prep_kernel(const float* __restrict__ pw,
                            const float* __restrict__ qw) {
    int i = blockIdx.x * blockDim.x + threadIdx.x;
    if (i < B * HW) g_Z[i] = 0.f;
    if (i < 2 * B * G) g_stats[i] = 0.f;
    if (i < C * C) {
        gb_pw[i] = __float2bfloat16(pw[i]);
        float w = qw[i];
        bf16 hi = __float2bfloat16(w);
        bf16 lo = __float2bfloat16(w - __bfloat162float(hi));
        int o = i / C, c = i - o * C;
        gb_qw[(size_t)o * KQ + c]         = hi;
        gb_qw[(size_t)o * KQ + C + c]     = hi;
        gb_qw[(size_t)o * KQ + 2 * C + c] = lo;
    }
}

// transpose qw/kw/vw (fp32 [r][c] -> bf16 [c][r])
__global__ void transpose3_kernel(const float* __restrict__ qw,
                                  const float* __restrict__ kw,
                                  const float* __restrict__ vw) {
    __shared__ float tile[32][33];
    const float* src = (blockIdx.z == 0) ? qw : (blockIdx.z == 1) ? kw : vw;
    bf16* dst = (blockIdx.z == 0) ? gb_qwT : (blockIdx.z == 1) ? gb_kwT : gb_vwT;
    int r0 = blockIdx.x << 5, c0 = blockIdx.y << 5;
    int tx = threadIdx.x, ty = threadIdx.y;  // 32 x 8
    #pragma unroll
    for (int kk = 0; kk < 4; kk++)
        tile[ty + kk * 8][tx] = src[(size_t)(r0 + ty + kk * 8) * C + c0 + tx];
    __syncthreads();
    #pragma unroll
    for (int kk = 0; kk < 4; kk++)
        dst[(size_t)(c0 + ty + kk * 8) * C + r0 + tx] =
            __float2bfloat16(tile[tx][ty + kk * 8]);
}

// g[c] = sum_o qb[o] kw[o][c];  bias2[o] = sum_c pw[o][c] vb[c] + pb[o]
__global__ void smallbias_kernel(const float* __restrict__ qb,
                                 const float* __restrict__ kw,
                                 const float* __restrict__ pw,
                                 const float* __restrict__ vb,
                                 const float* __restrict__ pb) {
    int i = threadIdx.x;  // 512 threads
    float s = 0.f;
    for (int o = 0; o < C; o++) s += qb[o] * kw[(size_t)o * C + i];
    g_g[i] = s;
    float s2 = 0.f;
    for (int c = 0; c < C; c++) s2 += pw[(size_t)i * C + c] * vb[c];
    g_b2[i] = s2 + pb[i];
}

// ---------------------------------------------------------------------------
// BF16 mma.sync GEMM: 128x128 tile, BK=64, 8 warps (2x4), warp 64x32,
// m16n8k16, 3-stage cp.async ring, one __syncthreads per K-tile.
// C[m,n] = alpha * sum_k A[m,k]*Bm[n,k] (+bias) (+skip^T). K-major operands.
// BIAS_MODE: 0 none, 1 bias[row m], 2 bias[col n].
// OUT: 0 = bf16 -> Cb, 1 = fp32 -> Cf, 2 = both.
// SM_MODE: 0 none, 1 = exp + row-sum atomics into Z (scores),
//          3 = scale acc by 1/Z[col] before bias/skip (proj).
// ---------------------------------------------------------------------------
constexpr int STAGE_BYTES = 2 * 128 * 128;     // A tile + B tile = 32 KB
constexpr int GEMM_SMEM = 3 * STAGE_BYTES;     // 98304 bytes

template <int BIAS_MODE, bool HAS_SKIP, int OUT, int SM_MODE>
__global__ __launch_bounds__(256, 2)
void mma_gemm(const bf16* __restrict__ A, int lda, long long sA,
              const bf16* __restrict__ Bm, int ldb, long long sB,
              float* __restrict__ Cf, bf16* __restrict__ Cb, int ldc, long long sC,
              int K, float alpha, const float* __restrict__ bias,
              const float* __restrict__ skip, int ldsk, long long sSk,
              float* __restrict__ Z) {
    extern __shared__ __align__(16) char dsm[];

    const int bz = blockIdx.z;
    A  += (size_t)bz * sA;
    Bm += (size_t)bz * sB;
    if (OUT != 0) Cf += (size_t)bz * sC;
    if (OUT != 1) Cb += (size_t)bz * sC;
    if (HAS_SKIP) skip += (size_t)bz * sSk;
    if (SM_MODE != 0) Z += (size_t)bz * HW;

    const int bm = blockIdx.x * 128, bn = blockIdx.y * 128;
    const int tid = threadIdx.x, wid = tid >> 5, lane = tid & 31;
    const int wm = wid & 1, wn = wid >> 1;      // warp grid 2 (M) x 4 (N)
    const int gr = lane >> 2, t4 = lane & 3;
    const int grp = lane >> 3, rowin = lane & 7;
    const int qhiA = grp >> 1;
    const int qhiB = grp & 1;

    // staging: thread -> row r = tid>>1, 16B chunks q0..q0+3 of that row
    const int r  = tid >> 1;
    const int q0 = (tid & 1) * 4;
    const bf16* Arow = A  + (size_t)(bm + r) * lda;
    const bf16* Brow = Bm + (size_t)(bn + r) * ldb;
    uint32_t off[4];
    #pragma unroll
    for (int j = 0; j < 4; j++)
        off[j] = r * 128 + (((q0 + j) ^ (r & 7)) << 4);   // bytes within 16KB tile
    const uint32_t smBase = smem_u32(dsm);
    // stage s at smBase + s*32KB: [A 16KB | B 16KB]
    auto stage = [&](int k0, int s) {
        uint32_t ab = smBase + s * STAGE_BYTES;
        uint32_t bb = ab + 16384;
        #pragma unroll
        for (int j = 0; j < 4; j++) {
            CP_ASYNC16(ab + off[j], Arow + k0 + (q0 + j) * 8);
            CP_ASYNC16(bb + off[j], Brow + k0 + (q0 + j) * 8);
        }
        CP_COMMIT;
    };

    // fragment row byte-offsets
    uint32_t aRow[4], bRow[2];
    #pragma unroll
    for (int mf = 0; mf < 4; mf++)
        aRow[mf] = (uint32_t)(wm * 64 + mf * 16 + (grp & 1) * 8 + rowin) * 128;
    #pragma unroll
    for (int p = 0; p < 2; p++)
        bRow[p] = (uint32_t)(wn * 32 + p * 16 + (grp >> 1) * 8 + rowin) * 128;

    float acc[4][4][4];
    #pragma unroll
    for (int i = 0; i < 4; i++)
        #pragma unroll
        for (int j = 0; j < 4; j++)
            #pragma unroll
            for (int q = 0; q < 4; q++) acc[i][j][q] = 0.f;

    const int nk = K >> 6;                      // BK = 64 bf16
    stage(0, 0);
    stage(64, 1);

    int s_cur = 0, s_nxt = 2;
    for (int kt = 0; kt < nk; kt++) {
        if (kt == nk - 1) { CP_WAIT0; } else { CP_WAIT1; }
        __syncthreads();
        if (kt + 2 < nk) stage((kt + 2) << 6, s_nxt);
        const uint32_t aB = smBase + s_cur * STAGE_BYTES;
        const uint32_t bB = aB + 16384;
        #pragma unroll
        for (int kk = 0; kk < 4; kk++) {        // 4 x K16 per tile
            uint32_t av[4][4], bv[4][2];
            #pragma unroll
            for (int mf = 0; mf < 4; mf++)
                ldm_x4(av[mf], aB + aRow[mf] + ((((kk << 1) + qhiA) ^ rowin) << 4));
            #pragma unroll
            for (int p = 0; p < 2; p++) {
                uint32_t t[4];
                ldm_x4(t, bB + bRow[p] + ((((kk << 1) + qhiB) ^ rowin) << 4));
                bv[2 * p][0] = t[0]; bv[2 * p][1] = t[1];
                bv[2 * p + 1][0] = t[2]; bv[2 * p + 1][1] = t[3];
            }
            #pragma unroll
            for (int mf = 0; mf < 4; mf++)
                #pragma unroll
                for (int nf = 0; nf < 4; nf++)
                    mma_bf16(acc[mf][nf], av[mf], bv[nf]);
        }
        s_cur = (s_cur + 1) % 3;
        s_nxt = (s_nxt + 1) % 3;
    }

    // epilogue
    float rsum[4][2];
    if (SM_MODE == 1) {
        #pragma unroll
        for (int i = 0; i < 4; i++) { rsum[i][0] = 0.f; rsum[i][1] = 0.f; }
    }
    #pragma unroll
    for (int mf = 0; mf < 4; mf++) {
        #pragma unroll
        for (int half = 0; half < 2; half++) {
            int rw = bm + wm * 64 + mf * 16 + gr + half * 8;
            float bvv = (BIAS_MODE == 1) ? bias[rw] : 0.f;
            #pragma unroll
            for (int nf = 0; nf < 4; nf++) {
                int cl = bn + wn * 32 + nf * 8 + t4 * 2;
                float ax = acc[mf][nf][half * 2 + 0] * alpha;
                float ay = acc[mf][nf][half * 2 + 1] * alpha;
                if (SM_MODE == 3) {
                    ax *= 1.f / Z[cl];
                    ay *= 1.f / Z[cl + 1];
                }
                float ox = ax + bvv;
                float oy = ay + bvv;
                if (BIAS_MODE == 2) { ox += bias[cl]; oy += bias[cl + 1]; }
                if (HAS_SKIP) {
                    ox += skip[(size_t)cl * ldsk + rw];
                    oy += skip[(size_t)(cl + 1) * ldsk + rw];
                }
                if (SM_MODE == 1) {
                    ox = __expf(ox); oy = __expf(oy);
                    rsum[mf][half] += ox + oy;
                }
                if (OUT != 0)
                    *reinterpret_cast<float2*>(&Cf[(size_t)rw * ldc + cl]) =
                        make_float2(ox, oy);
                if (OUT != 1)
                    *reinterpret_cast<bf162*>(&Cb[(size_t)rw * ldc + cl]) =
                        __floats2bfloat162_rn(ox, oy);
            }
        }
    }

    if (SM_MODE == 1) {
        float* zs = reinterpret_cast<float*>(dsm);   // [128 rows][4 wn]
        __syncthreads();
        #pragma unroll
        for (int mf = 0; mf < 4; mf++) {
            #pragma unroll
            for (int half = 0; half < 2; half++) {
                float s = rsum[mf][half];
                s += __shfl_xor_sync(0xffffffffu, s, 1);
                s += __shfl_xor_sync(0xffffffffu, s, 2);
                if (t4 == 0) {
                    int rloc = wm * 64 + mf * 16 + gr + half * 8;
                    zs[rloc * 4 + wn] = s;
                }
            }
        }
        __syncthreads();
        if (tid < 128) {
            float s = zs[tid * 4] + zs[tid * 4 + 1] + zs[tid * 4 + 2] + zs[tid * 4 + 3];
            atomicAdd(&Z[bm + tid], s);
        }
    }
}

// ---------------------------------------------------------------------------
// Launch
// ---------------------------------------------------------------------------
extern "C" void kernel_launch(void* const* d_in, const int* in_sizes, int n_in,
                              void* d_out, int out_size) {
    const float* x   = (const float*)d_in[0];
    const float* nsc = (const float*)d_in[1];
    const float* nbi = (const float*)d_in[2];
    const float* q_w = (const float*)d_in[3];
    const float* q_b = (const float*)d_in[4];
    const float* k_w = (const float*)d_in[5];
    const float* k_b = (const float*)d_in[6];
    const float* v_w = (const float*)d_in[7];
    const float* v_b = (const float*)d_in[8];
    const float* p_w = (const float*)d_in[9];
    const float* p_b = (const float*)d_in[10];
    float* out = (float*)d_out;
    (void)k_b;  // row-constant in softmax: cancels exactly

    bf16 *hntb, *hncm, *hqb, *qw2b, *scb, *ub, *pwb, *qwT, *kwT, *vwT, *wtb, *mmb, *qwb;
    float *qt, *Z, *gv, *b2;
    cudaGetSymbolAddress((void**)&hntb, gb_hnt);
    cudaGetSymbolAddress((void**)&hncm, gb_hncm);
    cudaGetSymbolAddress((void**)&hqb,  gb_hq);
    cudaGetSymbolAddress((void**)&qt,   g_qt);
    cudaGetSymbolAddress((void**)&qw2b, gb_qw2);
    cudaGetSymbolAddress((void**)&scb,  gb_sc);
    cudaGetSymbolAddress((void**)&ub,   gb_u);
    cudaGetSymbolAddress((void**)&pwb,  gb_pw);
    cudaGetSymbolAddress((void**)&qwT,  gb_qwT);
    cudaGetSymbolAddress((void**)&kwT,  gb_kwT);
    cudaGetSymbolAddress((void**)&vwT,  gb_vwT);
    cudaGetSymbolAddress((void**)&wtb,  gb_wt);
    cudaGetSymbolAddress((void**)&mmb,  gb_mm);
    cudaGetSymbolAddress((void**)&qwb,  gb_qw);
    cudaGetSymbolAddress((void**)&gv,   g_g);
    cudaGetSymbolAddress((void**)&b2,   g_b2);
    cudaGetSymbolAddress((void**)&Z,    g_Z);

    cudaFuncSetAttribute(mma_gemm<0, false, 0, 0>, cudaFuncAttributeMaxDynamicSharedMemorySize, GEMM_SMEM);
    cudaFuncSetAttribute(mma_gemm<0, false, 0, 1>, cudaFuncAttributeMaxDynamicSharedMemorySize, GEMM_SMEM);
    cudaFuncSetAttribute(mma_gemm<2, false, 0, 0>, cudaFuncAttributeMaxDynamicSharedMemorySize, GEMM_SMEM);
    cudaFuncSetAttribute(mma_gemm<2, false, 1, 0>, cudaFuncAttributeMaxDynamicSharedMemorySize, GEMM_SMEM);
    cudaFuncSetAttribute(mma_gemm<1, true,  1, 3>, cudaFuncAttributeMaxDynamicSharedMemorySize, GEMM_SMEM);

    const long long sHnt = (long long)N3 * C;
    const long long sHq  = (long long)HW * KQ;
    const long long sQt  = (long long)HW * C;
    const long long sSc  = (long long)HW * N3;
    const long long sCm  = (long long)C * N3;

    // Prep: zero + pw bf16 + qw split; transposes; small bias vectors
    prep_kernel<<<(C * C + 255) / 256, 256>>>(p_w, q_w);
    transpose3_kernel<<<dim3(16, 16, 3), dim3(32, 8)>>>(q_w, k_w, v_w);
    smallbias_kernel<<<1, C>>>(q_b, k_w, p_w, v_b, p_b);

    // GroupNorm
    gn_stats_kernel<<<dim3(B * G, 16), 256>>>(x);
    gn_apply_t_kernel<<<dim3(HW / 32, C / 32, B * T), dim3(32, 8)>>>(x, nsc, nbi);

    // Wt[c][j] = sum_o kw[o][c] qw[o][j]   (4x4 grid, K=512)
    mma_gemm<0, false, 0, 0><<<dim3(C / 128, C / 128, 1), 256, GEMM_SMEM>>>(
        kwT, C, 0, qwT, C, 0, nullptr, wtb, C, 0, C, 1.f,
        nullptr, nullptr, 0, 0, nullptr);

    // M[o][j] = sum_c pw[o][c] vw[c][j]
    mma_gemm<0, false, 0, 0><<<dim3(C / 128, C / 128, 1), 256, GEMM_SMEM>>>(
        pwb, C, 0, vwT, C, 0, nullptr, mmb, C, 0, C, 1.f,
        nullptr, nullptr, 0, 0, nullptr);

    // q (split-bf16, K=1536): qt[p][o] fp32 (skip path) + q_b[o]
    mma_gemm<2, false, 1, 0><<<dim3(HW / 128, C / 128, B), 256, GEMM_SMEM>>>(
        hqb, KQ, sHq, qwb, KQ, 0, qt, nullptr, C, sQt, KQ, 1.f, q_b,
        nullptr, 0, 0, nullptr);

    // qw2[p][c] = sum_j hn1[p][j] Wt[c][j] + g[c]
    mma_gemm<2, false, 0, 0><<<dim3(HW / 128, C / 128, B), 256, GEMM_SMEM>>>(
        hntb + (size_t)HW * C, C, sHnt, wtb, C, 0, nullptr, qw2b, C, sQt,
        C, 1.f, gv, nullptr, 0, 0, nullptr);

    // e[p][m] = exp(alpha * sum_c qw2[p][c] hn[m][c]); Z[p] += row sums
    mma_gemm<0, false, 0, 1><<<dim3(HW / 128, N3 / 128, B), 256, GEMM_SMEM>>>(
        qw2b, C, sQt, hntb, C, sHnt, nullptr, scb, N3, sSc, C,
        ALPHA, nullptr, nullptr, 0, 0, Z);

    // u[p][j] = sum_m e[p][m] hn[j][m]
    mma_gemm<0, false, 0, 0><<<dim3(HW / 128, C / 128, B), 256, GEMM_SMEM>>>(
        scb, N3, sSc, hncm, N3, sCm, nullptr, ub, C, sQt, N3, 1.f,
        nullptr, nullptr, 0, 0, nullptr);

    // out[o][p] = (sum_j M[o][j] u[p][j]) / Z[p] + bias2[o] + qt[p][o]
    mma_gemm<1, true, 1, 3><<<dim3(C / 128, HW / 128, B), 256, GEMM_SMEM>>>(
        mmb, C, 0, ub, C, sQt, out, nullptr, HW, (long long)C * HW, C, 1.f, b2,
        qt, C, sQt, Z);
}

// round 17
// speedup vs baseline: 1.1426x; 1.1426x over previous
#include <cuda_runtime.h>
#include <cuda_bf16.h>
#include <cstdint>

constexpr int B  = 4;
constexpr int C  = 512;
constexpr int T  = 3;
constexpr int HW = 2304;   // 48*48
constexpr int N3 = 6912;   // 3*HW
constexpr int G  = 4;
constexpr int CG = C / G;  // 128
constexpr int KQ = 3 * C;  // 1536: split-bf16 concat K for q
constexpr float EPS = 1e-6f;

typedef __nv_bfloat16  bf16;
typedef __nv_bfloat162 bf162;

// Scratch
__device__ bf16  gb_hnt[(size_t)B * N3 * C];   // normalized, transposed, bf16
__device__ bf16  gb_hq [(size_t)B * HW * KQ];  // t=1 slice split [hi|lo|hi]
__device__ float g_qt  [(size_t)B * HW * C];   // q fp32 (skip)
__device__ bf16  gb_qt [(size_t)B * HW * C];   // q bf16 (scores operand)
__device__ bf16  gb_kt [(size_t)B * N3 * C];   // k [m][c]
__device__ bf16  gb_v  [(size_t)B * C * N3];   // v [c][m]
__device__ bf16  gb_sc [(size_t)B * HW * N3];  // exp(scores) [p][m]
__device__ bf16  gb_ot [(size_t)B * HW * C];   // attn out [p][c]
__device__ bf16  gb_kw[C * C], gb_vw[C * C], gb_pw[C * C];
__device__ bf16  gb_qw[C * KQ];                // q weights split [hi|hi|lo]
__device__ float g_stats[2 * B * G];
__device__ float g_Z[(size_t)B * HW];          // softmax denominators

__device__ __forceinline__ uint32_t smem_u32(const void* p) {
    return (uint32_t)__cvta_generic_to_shared(p);
}
#define CP_ASYNC16(sm, gm) \
    asm volatile("cp.async.cg.shared.global [%0], [%1], 16;" :: "r"(sm), "l"(gm))
#define CP_COMMIT asm volatile("cp.async.commit_group;")
#define CP_WAIT1  asm volatile("cp.async.wait_group 1;")
#define CP_WAIT0  asm volatile("cp.async.wait_group 0;")

__device__ __forceinline__ void ldm_x4(uint32_t* r, uint32_t addr) {
    asm volatile("ldmatrix.sync.aligned.m8n8.x4.shared.b16 {%0,%1,%2,%3}, [%4];"
        : "=r"(r[0]), "=r"(r[1]), "=r"(r[2]), "=r"(r[3]) : "r"(addr));
}
__device__ __forceinline__ void mma_bf16(float* c, const uint32_t* a, const uint32_t* b) {
    asm volatile("mma.sync.aligned.m16n8k16.row.col.f32.bf16.bf16.f32 "
        "{%0,%1,%2,%3}, {%4,%5,%6,%7}, {%8,%9}, {%0,%1,%2,%3};"
        : "+f"(c[0]), "+f"(c[1]), "+f"(c[2]), "+f"(c[3])
        : "r"(a[0]), "r"(a[1]), "r"(a[2]), "r"(a[3]), "r"(b[0]), "r"(b[1]));
}

// ---------------------------------------------------------------------------
// GroupNorm stats (grid.y = 32 slices for higher memory-level parallelism)
// ---------------------------------------------------------------------------
__global__ void gn_stats_kernel(const float* __restrict__ x) {
    const int bg = blockIdx.x;
    const int b = bg >> 2, g = bg & 3;
    const int TOT4 = CG * T * HW / 4;      // 221184
    const int PER  = TOT4 / 32;            // 6912 float4 per slice
    const int start = blockIdx.y * PER;

    float s = 0.f, ss = 0.f;
    for (int i = start + threadIdx.x; i < start + PER; i += blockDim.x) {
        int cl = i / (T * HW / 4);
        int r  = i - cl * (T * HW / 4);
        int t  = r / (HW / 4);
        int p4 = r - t * (HW / 4);
        float4 v = reinterpret_cast<const float4*>(x)[
            ((size_t)(t * B + b) * C + g * CG + cl) * (HW / 4) + p4];
        s  += v.x + v.y + v.z + v.w;
        ss += v.x * v.x + v.y * v.y + v.z * v.z + v.w * v.w;
    }
    __shared__ float rs[8], rss[8];
    #pragma unroll
    for (int o = 16; o; o >>= 1) {
        s  += __shfl_xor_sync(0xffffffffu, s, o);
        ss += __shfl_xor_sync(0xffffffffu, ss, o);
    }
    if ((threadIdx.x & 31) == 0) { rs[threadIdx.x >> 5] = s; rss[threadIdx.x >> 5] = ss; }
    __syncthreads();
    if (threadIdx.x == 0) {
        float a = 0.f, c = 0.f;
        #pragma unroll
        for (int i = 0; i < 8; i++) { a += rs[i]; c += rss[i]; }
        atomicAdd(&g_stats[2 * bg],     a);
        atomicAdd(&g_stats[2 * bg + 1], c);
    }
}

// normalize + affine + transpose -> gb_hnt (bf16); t=1 slice split hi/lo
__global__ void gn_apply_t_kernel(const float* __restrict__ x,
                                  const float* __restrict__ scale,
                                  const float* __restrict__ bias) {
    __shared__ float tile[32][33];
    const int bt = blockIdx.z;
    const int b = bt / T, t = bt - b * T;
    const int p0 = blockIdx.x << 5, c0 = blockIdx.y << 5;
    const int tx = threadIdx.x, ty = threadIdx.y;  // 32 x 8
    const float nrm = 1.f / (float)(CG * T * HW);

    #pragma unroll
    for (int kk = 0; kk < 4; kk++) {
        int c = c0 + ty + kk * 8;
        int g = c >> 7;
        float sum = g_stats[2 * (b * G + g)];
        float sq  = g_stats[2 * (b * G + g) + 1];
        float mean = sum * nrm;
        float var  = sq * nrm - mean * mean;
        float rstd = rsqrtf(var + EPS);
        float a = rstd * scale[c];
        float d = bias[c] - mean * a;
        float v = x[((size_t)(t * B + b) * C + c) * HW + p0 + tx];
        tile[ty + kk * 8][tx] = v * a + d;
    }
    __syncthreads();
    #pragma unroll
    for (int kk = 0; kk < 4; kk++) {
        int p = p0 + ty + kk * 8;
        float v = tile[tx][ty + kk * 8];
        bf16 hi = __float2bfloat16(v);
        gb_hnt[(size_t)b * N3 * C + (size_t)(t * HW + p) * C + c0 + tx] = hi;
        if (t == 1) {
            bf16 lo = __float2bfloat16(v - __bfloat162float(hi));
            size_t base = ((size_t)b * HW + p) * KQ + c0 + tx;
            gb_hq[base]            = hi;
            gb_hq[base + C]        = lo;
            gb_hq[base + 2 * C]    = hi;
        }
    }
}

// Convert weights + zero Z/stats (merged prep kernel)
__global__ void prep_kernel(const float* __restrict__ kw,
                            const float* __restrict__ vw,
                            const float* __restrict__ pw,
                            const float* __restrict__ qw) {
    int i = blockIdx.x * blockDim.x + threadIdx.x;
    if (i < B * HW) g_Z[i] = 0.f;
    if (i < 2 * B * G) g_stats[i] = 0.f;
    if (i < C * C) {
        gb_kw[i] = __float2bfloat16(kw[i]);
        gb_vw[i] = __float2bfloat16(vw[i]);
        gb_pw[i] = __float2bfloat16(pw[i]);
        float w = qw[i];
        bf16 hi = __float2bfloat16(w);
        bf16 lo = __float2bfloat16(w - __bfloat162float(hi));
        int o = i / C, c = i - o * C;
        gb_qw[(size_t)o * KQ + c]         = hi;
        gb_qw[(size_t)o * KQ + C + c]     = hi;
        gb_qw[(size_t)o * KQ + 2 * C + c] = lo;
    }
}

// ---------------------------------------------------------------------------
// BF16 mma.sync GEMM: 128x128 tile, BK=64, 8 warps (2x4), warp 64x32,
// m16n8k16, 3-stage cp.async ring, one __syncthreads per K-tile,
// quad-XOR swizzle.
// C[m,n] = alpha * sum_k A[m,k]*Bm[n,k] (+bias) (+skip^T). K-major operands.
// BIAS_MODE: 0 none, 1 bias[row m], 2 bias[col n].
// OUT: 0 = bf16 -> Cb, 1 = fp32 -> Cf, 2 = both.
// SM_MODE: 0 none, 1 = exp + row-sum atomics into Z (scores),
//          2 = scale output rows by 1/Z[row] (attn*V).
// ---------------------------------------------------------------------------
constexpr int STAGE_BYTES = 2 * 128 * 128;     // A tile + B tile = 32 KB
constexpr int GEMM_SMEM = 3 * STAGE_BYTES;     // 98304 bytes

template <int BIAS_MODE, bool HAS_SKIP, int OUT, int SM_MODE>
__global__ __launch_bounds__(256, 2)
void mma_gemm(const bf16* __restrict__ A, int lda, long long sA,
              const bf16* __restrict__ Bm, int ldb, long long sB,
              float* __restrict__ Cf, bf16* __restrict__ Cb, int ldc, long long sC,
              int K, float alpha, const float* __restrict__ bias,
              const float* __restrict__ skip, int ldsk, long long sSk,
              float* __restrict__ Z) {
    extern __shared__ __align__(16) char dsm[];

    const int bz = blockIdx.z;
    A  += (size_t)bz * sA;
    Bm += (size_t)bz * sB;
    if (OUT != 0) Cf += (size_t)bz * sC;
    if (OUT != 1) Cb += (size_t)bz * sC;
    if (HAS_SKIP) skip += (size_t)bz * sSk;
    if (SM_MODE != 0) Z += (size_t)bz * HW;

    const int bm = blockIdx.x * 128, bn = blockIdx.y * 128;
    const int tid = threadIdx.x, wid = tid >> 5, lane = tid & 31;
    const int wm = wid & 1, wn = wid >> 1;      // warp grid 2 (M) x 4 (N)
    const int gr = lane >> 2, t4 = lane & 3;
    const int grp = lane >> 3, rowin = lane & 7;
    const int qhiA = grp >> 1;
    const int qhiB = grp & 1;

    // staging: thread -> row r = tid>>1, 16B chunks q0..q0+3 of that row
    const int r  = tid >> 1;
    const int q0 = (tid & 1) * 4;
    const bf16* Arow = A  + (size_t)(bm + r) * lda;
    const bf16* Brow = Bm + (size_t)(bn + r) * ldb;
    uint32_t off[4];
    #pragma unroll
    for (int j = 0; j < 4; j++)
        off[j] = r * 128 + (((q0 + j) ^ (r & 7)) << 4);   // bytes within 16KB tile
    const uint32_t smBase = smem_u32(dsm);
    // stage s at smBase + s*32KB: [A 16KB | B 16KB]
    auto stage = [&](int k0, int s) {
        uint32_t ab = smBase + s * STAGE_BYTES;
        uint32_t bb = ab + 16384;
        #pragma unroll
        for (int j = 0; j < 4; j++) {
            CP_ASYNC16(ab + off[j], Arow + k0 + (q0 + j) * 8);
            CP_ASYNC16(bb + off[j], Brow + k0 + (q0 + j) * 8);
        }
        CP_COMMIT;
    };

    // fragment row byte-offsets
    uint32_t aRow[4], bRow[2];
    #pragma unroll
    for (int mf = 0; mf < 4; mf++)
        aRow[mf] = (uint32_t)(wm * 64 + mf * 16 + (grp & 1) * 8 + rowin) * 128;
    #pragma unroll
    for (int p = 0; p < 2; p++)
        bRow[p] = (uint32_t)(wn * 32 + p * 16 + (grp >> 1) * 8 + rowin) * 128;

    float acc[4][4][4];
    #pragma unroll
    for (int i = 0; i < 4; i++)
        #pragma unroll
        for (int j = 0; j < 4; j++)
            #pragma unroll
            for (int q = 0; q < 4; q++) acc[i][j][q] = 0.f;

    const int nk = K >> 6;                      // BK = 64 bf16
    stage(0, 0);
    stage(64, 1);

    int s_cur = 0, s_nxt = 2;
    for (int kt = 0; kt < nk; kt++) {
        if (kt == nk - 1) { CP_WAIT0; } else { CP_WAIT1; }
        __syncthreads();
        if (kt + 2 < nk) stage((kt + 2) << 6, s_nxt);
        const uint32_t aB = smBase + s_cur * STAGE_BYTES;
        const uint32_t bB = aB + 16384;
        #pragma unroll
        for (int kk = 0; kk < 4; kk++) {        // 4 x K16 per tile
            uint32_t av[4][4], bv[4][2];
            #pragma unroll
            for (int mf = 0; mf < 4; mf++)
                ldm_x4(av[mf], aB + aRow[mf] + ((((kk << 1) + qhiA) ^ rowin) << 4));
            #pragma unroll
            for (int p = 0; p < 2; p++) {
                uint32_t t[4];
                ldm_x4(t, bB + bRow[p] + ((((kk << 1) + qhiB) ^ rowin) << 4));
                bv[2 * p][0] = t[0]; bv[2 * p][1] = t[1];
                bv[2 * p + 1][0] = t[2]; bv[2 * p + 1][1] = t[3];
            }
            #pragma unroll
            for (int mf = 0; mf < 4; mf++)
                #pragma unroll
                for (int nf = 0; nf < 4; nf++)
                    mma_bf16(acc[mf][nf], av[mf], bv[nf]);
        }
        s_cur = (s_cur + 1) % 3;
        s_nxt = (s_nxt + 1) % 3;
    }

    // epilogue
    float rsum[4][2];
    if (SM_MODE == 1) {
        #pragma unroll
        for (int i = 0; i < 4; i++) { rsum[i][0] = 0.f; rsum[i][1] = 0.f; }
    }
    #pragma unroll
    for (int mf = 0; mf < 4; mf++) {
        #pragma unroll
        for (int half = 0; half < 2; half++) {
            int rw = bm + wm * 64 + mf * 16 + gr + half * 8;
            float bvv = (BIAS_MODE == 1) ? bias[rw] : 0.f;
            float zinv = 1.f;
            if (SM_MODE == 2) zinv = 1.f / Z[rw];
            #pragma unroll
            for (int nf = 0; nf < 4; nf++) {
                int cl = bn + wn * 32 + nf * 8 + t4 * 2;
                float ox = acc[mf][nf][half * 2 + 0] * alpha + bvv;
                float oy = acc[mf][nf][half * 2 + 1] * alpha + bvv;
                if (BIAS_MODE == 2) { ox += bias[cl]; oy += bias[cl + 1]; }
                if (HAS_SKIP) {
                    ox += skip[(size_t)cl * ldsk + rw];
                    oy += skip[(size_t)(cl + 1) * ldsk + rw];
                }
                if (SM_MODE == 1) {
                    ox = __expf(ox); oy = __expf(oy);
                    rsum[mf][half] += ox + oy;
                }
                if (SM_MODE == 2) { ox *= zinv; oy *= zinv; }
                if (OUT != 0)
                    *reinterpret_cast<float2*>(&Cf[(size_t)rw * ldc + cl]) =
                        make_float2(ox, oy);
                if (OUT != 1)
                    *reinterpret_cast<bf162*>(&Cb[(size_t)rw * ldc + cl]) =
                        __floats2bfloat162_rn(ox, oy);
            }
        }
    }

    if (SM_MODE == 1) {
        // reduce rsum across t4 quad, stash per-warp partials in smem, then
        // one atomicAdd per CTA row into Z.
        float* zs = reinterpret_cast<float*>(dsm);   // [128 rows][4 wn]
        __syncthreads();   // smem buffers no longer needed by mainloop
        #pragma unroll
        for (int mf = 0; mf < 4; mf++) {
            #pragma unroll
            for (int half = 0; half < 2; half++) {
                float s = rsum[mf][half];
                s += __shfl_xor_sync(0xffffffffu, s, 1);
                s += __shfl_xor_sync(0xffffffffu, s, 2);
                if (t4 == 0) {
                    int rloc = wm * 64 + mf * 16 + gr + half * 8;
                    zs[rloc * 4 + wn] = s;
                }
            }
        }
        __syncthreads();
        if (tid < 128) {
            float s = zs[tid * 4] + zs[tid * 4 + 1] + zs[tid * 4 + 2] + zs[tid * 4 + 3];
            atomicAdd(&Z[bm + tid], s);
        }
    }
}

// ---------------------------------------------------------------------------
// Launch
// ---------------------------------------------------------------------------
extern "C" void kernel_launch(void* const* d_in, const int* in_sizes, int n_in,
                              void* d_out, int out_size) {
    const float* x   = (const float*)d_in[0];
    const float* nsc = (const float*)d_in[1];
    const float* nbi = (const float*)d_in[2];
    const float* q_w = (const float*)d_in[3];
    const float* q_b = (const float*)d_in[4];
    const float* k_w = (const float*)d_in[5];
    const float* k_b = (const float*)d_in[6];
    const float* v_w = (const float*)d_in[7];
    const float* v_b = (const float*)d_in[8];
    const float* p_w = (const float*)d_in[9];
    const float* p_b = (const float*)d_in[10];
    float* out = (float*)d_out;

    bf16 *hntb, *hqb, *qtb, *ktb, *vb, *scb, *otb, *kwb, *vwb, *pwb, *qwb;
    float *qt, *Z;
    cudaGetSymbolAddress((void**)&hntb, gb_hnt);
    cudaGetSymbolAddress((void**)&hqb,  gb_hq);
    cudaGetSymbolAddress((void**)&qt,   g_qt);
    cudaGetSymbolAddress((void**)&qtb,  gb_qt);
    cudaGetSymbolAddress((void**)&ktb,  gb_kt);
    cudaGetSymbolAddress((void**)&vb,   gb_v);
    cudaGetSymbolAddress((void**)&scb,  gb_sc);
    cudaGetSymbolAddress((void**)&otb,  gb_ot);
    cudaGetSymbolAddress((void**)&kwb,  gb_kw);
    cudaGetSymbolAddress((void**)&vwb,  gb_vw);
    cudaGetSymbolAddress((void**)&pwb,  gb_pw);
    cudaGetSymbolAddress((void**)&qwb,  gb_qw);
    cudaGetSymbolAddress((void**)&Z,    g_Z);

    cudaFuncSetAttribute(mma_gemm<0, false, 0, 1>, cudaFuncAttributeMaxDynamicSharedMemorySize, GEMM_SMEM);
    cudaFuncSetAttribute(mma_gemm<0, false, 0, 2>, cudaFuncAttributeMaxDynamicSharedMemorySize, GEMM_SMEM);
    cudaFuncSetAttribute(mma_gemm<1, false, 0, 0>, cudaFuncAttributeMaxDynamicSharedMemorySize, GEMM_SMEM);
    cudaFuncSetAttribute(mma_gemm<2, false, 0, 0>, cudaFuncAttributeMaxDynamicSharedMemorySize, GEMM_SMEM);
    cudaFuncSetAttribute(mma_gemm<2, false, 2, 0>, cudaFuncAttributeMaxDynamicSharedMemorySize, GEMM_SMEM);
    cudaFuncSetAttribute(mma_gemm<1, true,  1, 0>, cudaFuncAttributeMaxDynamicSharedMemorySize, GEMM_SMEM);

    const long long sHnt = (long long)N3 * C;
    const long long sHq  = (long long)HW * KQ;
    const long long sQt  = (long long)HW * C;
    const long long sKt  = (long long)N3 * C;
    const long long sV   = (long long)C * N3;
    const long long sSc  = (long long)HW * N3;
    const long long sOt  = (long long)HW * C;

    // Prep (zero + weight convert), GroupNorm (+ transpose)
    prep_kernel<<<(C * C + 255) / 256, 256>>>(k_w, v_w, p_w, q_w);
    gn_stats_kernel<<<dim3(B * G, 32), 256>>>(x);
    gn_apply_t_kernel<<<dim3(HW / 32, C / 32, B * T), dim3(32, 8)>>>(x, nsc, nbi);

    // q (split-bf16 compensated, K=1536): qt[p][o] fp32 + bf16, + q_b[o]
    mma_gemm<2, false, 2, 0><<<dim3(HW / 128, C / 128, B), 256, GEMM_SMEM>>>(
        hqb, KQ, sHq, qwb, KQ, 0, qt, qtb, C, sQt, KQ, 1.f, q_b,
        nullptr, 0, 0, nullptr);

    // kt[m][o] = hnt[m][:] . k_w[o][:] + k_b[o]
    mma_gemm<2, false, 0, 0><<<dim3(N3 / 128, C / 128, B), 256, GEMM_SMEM>>>(
        hntb, C, sHnt, kwb, C, 0, nullptr, ktb, C, sKt, C, 1.f, k_b,
        nullptr, 0, 0, nullptr);

    // v[c][m] = v_w[c][:] . hnt[m][:] + v_b[c]
    mma_gemm<1, false, 0, 0><<<dim3(C / 128, N3 / 128, B), 256, GEMM_SMEM>>>(
        vwb, C, 0, hntb, C, sHnt, nullptr, vb, N3, sV, C, 1.f, v_b,
        nullptr, 0, 0, nullptr);

    // e[p][m] = exp((qt[p][:] . kt[m][:]) * C^-0.5); Z[p] += row sums
    mma_gemm<0, false, 0, 1><<<dim3(HW / 128, N3 / 128, B), 256, GEMM_SMEM>>>(
        qtb, C, sQt, ktb, C, sKt, nullptr, scb, N3, sSc, C,
        0.044194173824159216f, nullptr, nullptr, 0, 0, Z);

    // ot[p][c] = (e[p][:] . v[c][:]) / Z[p]
    mma_gemm<0, false, 0, 2><<<dim3(HW / 128, C / 128, B), 256, GEMM_SMEM>>>(
        scb, N3, sSc, vb, N3, sV, nullptr, otb, C, sOt, N3, 1.f,
        nullptr, nullptr, 0, 0, Z);

    // out[o][p] = p_w[o][:] . ot[p][:] + p_b[o] + qt[p][o]   (fp32 out)
    mma_gemm<1, true, 1, 0><<<dim3(C / 128, HW / 128, B), 256, GEMM_SMEM>>>(
        pwb, C, 0, otb, C, sOt, out, nullptr, HW, (long long)C * HW, C, 1.f, p_b,
        qt, C, sQt, nullptr);
}